// round 17
// baseline (speedup 1.0000x reference)
#include <cuda_runtime.h>

#define NN   100000
#define NEMAX 1000000
#define DD   64
#define NG   1024
#define NL   4
#define OUTD 16
#define MEGA_CTAS 128
#define MEGA_THREADS 512
#define CHUNK 784   // >= ceil(100000/128)=782

// Scratch (static __device__ arrays per harness rules)
__device__ float g_bufA[NN * DD];
__device__ float g_bufB[NN * DD];
__device__ float g_agg[NN * DD];
__device__ float g_pool[NG * DD];
__device__ int   g_rowStart[NN + 1];
__device__ int   g_cursor[NN];
__device__ int   g_bsum[MEGA_CTAS];
__device__ int   g_csrSrc[NEMAX];

// Grid barrier state: cnt returns to 0 after each barrier; phase is monotonic
// (relative comparison), so this is safe across graph replays.
__device__ unsigned g_barCnt = 0;
__device__ volatile unsigned g_barPhase = 0;

typedef unsigned long long u64;

__device__ __forceinline__ u64 pack2(float x) {
    u64 r;
    asm("mov.b64 %0, {%1, %1};" : "=l"(r) : "f"(x));
    return r;
}
__device__ __forceinline__ void fma2(u64 &d, u64 a, u64 b) {
    asm("fma.rn.f32x2 %0, %1, %2, %0;" : "+l"(d) : "l"(a), "l"(b));
}
__device__ __forceinline__ void add2(u64 &d, u64 a) {
    asm("add.rn.f32x2 %0, %0, %1;" : "+l"(d) : "l"(a));
}
__device__ __forceinline__ void unpack2(u64 v, float &lo, float &hi) {
    asm("mov.b64 {%0, %1}, %2;" : "=f"(lo), "=f"(hi) : "l"(v));
}

__device__ __forceinline__ void grid_bar() {
    __syncthreads();
    if (threadIdx.x == 0) {
        unsigned ph = g_barPhase;
        __threadfence();
        if (atomicAdd(&g_barCnt, 1u) == (unsigned)(MEGA_CTAS - 1)) {
            g_barCnt = 0;
            __threadfence();
            g_barPhase = ph + 1;
        } else {
            while (g_barPhase == ph) { }
        }
        __threadfence();
    }
    __syncthreads();
}

// ---------- One-kernel CSR build + pool zero (persistent, single wave) ----
__global__ void __launch_bounds__(MEGA_THREADS) csr_mega_kernel(
    const int *__restrict__ src, const int *__restrict__ dst,
    int nE, int nN,
    int *__restrict__ rowStart, int *__restrict__ cursor,
    int *__restrict__ csrSrc, int *__restrict__ bsum,
    float4 *__restrict__ pool4, int n4pool) {
    __shared__ int sC[CHUNK];
    __shared__ int sh[MEGA_THREADS];

    int tid = threadIdx.x;
    int cta = blockIdx.x;
    int gsz = MEGA_CTAS * MEGA_THREADS;
    int gid = cta * MEGA_THREADS + tid;

    // phase0: zero degree array (rowStart[0..nN)) + pool
    for (int i = gid; i < nN; i += gsz) rowStart[i] = 0;
    for (int i = gid; i < n4pool; i += gsz)
        pool4[i] = make_float4(0.f, 0.f, 0.f, 0.f);
    grid_bar();

    // phase1: histogram of dst
    for (int i = gid; i < nE; i += gsz) atomicAdd(&rowStart[dst[i]], 1);
    grid_bar();

    // phase2: per-CTA local exclusive scan of its node chunk (kept in smem)
    int chunk = (nN + MEGA_CTAS - 1) / MEGA_CTAS;
    int base = cta * chunk;
    int cnt = nN - base;
    if (cnt > chunk) cnt = chunk;
    if (cnt < 0) cnt = 0;

    for (int i = tid; i < cnt; i += MEGA_THREADS) sC[i] = rowStart[base + i];
    __syncthreads();

    int carry = 0;
    for (int t0 = 0; t0 < cnt; t0 += MEGA_THREADS) {
        int v = (t0 + tid < cnt) ? sC[t0 + tid] : 0;
        sh[tid] = v;
        __syncthreads();
        for (int off = 1; off < MEGA_THREADS; off <<= 1) {
            int u = (tid >= off) ? sh[tid - off] : 0;
            __syncthreads();
            sh[tid] += u;
            __syncthreads();
        }
        if (t0 + tid < cnt) sC[t0 + tid] = sh[tid] - v + carry;
        int tileTotal = sh[MEGA_THREADS - 1];
        __syncthreads();
        carry += tileTotal;
    }
    if (tid == 0) bsum[cta] = carry;
    grid_bar();

    // phase3: CTA0 exclusive-scans the 128 block totals
    if (cta == 0) {
        int v = (tid < MEGA_CTAS) ? bsum[tid] : 0;
        sh[tid] = v;
        __syncthreads();
        for (int off = 1; off < MEGA_THREADS; off <<= 1) {
            int u = (tid >= off) ? sh[tid - off] : 0;
            __syncthreads();
            sh[tid] += u;
            __syncthreads();
        }
        if (tid < MEGA_CTAS) bsum[tid] = sh[tid] - v;
    }
    grid_bar();

    // phase4: apply block offset; write rowStart + cursor
    int off0 = bsum[cta];
    for (int i = tid; i < cnt; i += MEGA_THREADS) {
        int rs = sC[i] + off0;
        rowStart[base + i] = rs;
        cursor[base + i] = rs;
    }
    if (cta == 0 && tid == 0) rowStart[nN] = nE;
    grid_bar();

    // phase5: fill CSR src lists
    for (int i = gid; i < nE; i += gsz) {
        int p = atomicAdd(&cursor[dst[i]], 1);
        csrSrc[p] = src[i];
    }
}

// ---------- Per-layer gather aggregation: agg[n] = sum_{j in N(n)} h[j] ----
// 16 threads/node (coalesced: half-warp covers one full 256B row).
// Rows loaded as ulonglong2 -> f32x2 packed adds (half the FADD issue slots).
__global__ void gather_kernel(const ulonglong2 *__restrict__ h2,
                              const int *__restrict__ rowStart,
                              const int *__restrict__ csrSrc,
                              ulonglong2 *__restrict__ agg2, int nNodes) {
    int t = blockIdx.x * blockDim.x + threadIdx.x;
    int n = t >> 4;
    if (n >= nNodes) return;
    int s = t & 15;
    int beg = rowStart[n];
    int end = rowStart[n + 1];

    u64 aLo = 0, aHi = 0, bLo = 0, bHi = 0;

    int j = beg;
    for (; j + 1 < end; j += 2) {
        int sa = __ldg(&csrSrc[j]);
        int sb = __ldg(&csrSrc[j + 1]);
        ulonglong2 va = h2[(size_t)sa * 16 + s];
        ulonglong2 vb = h2[(size_t)sb * 16 + s];
        add2(aLo, va.x); add2(aHi, va.y);
        add2(bLo, vb.x); add2(bHi, vb.y);
    }
    if (j < end) {
        int sa = __ldg(&csrSrc[j]);
        ulonglong2 va = h2[(size_t)sa * 16 + s];
        add2(aLo, va.x); add2(aHi, va.y);
    }
    add2(aLo, bLo);
    add2(aHi, bHi);

    ulonglong2 o;
    o.x = aLo; o.y = aHi;
    agg2[(size_t)n * 16 + s] = o;
}

// Fused: out = relu(agg @ Wrel + brel + h @ Wroot).
// 2 rows per thread (256-row tile per CTA) so each weight LDS feeds both rows.
// If isLast: instead of storing h, reduce relu'ed row into pool[batch[row]].
__global__ void __launch_bounds__(128) layer_kernel(
    const float4 *__restrict__ A4, const float4 *__restrict__ H4,
    const float *__restrict__ Wrel, const float *__restrict__ Wroot,
    const float *__restrict__ brel, float4 *__restrict__ Out4,
    const int *__restrict__ batch, float *__restrict__ pool,
    int nRows, int isLast) {
    __shared__ __align__(16) float sWr[DD * DD];
    __shared__ __align__(16) float sWo[DD * DD];
    __shared__ __align__(16) float sB[DD];

    int tid = threadIdx.x;
    for (int i = tid; i < DD * DD / 4; i += 128) {
        ((float4 *)sWr)[i] = ((const float4 *)Wrel)[i];
        ((float4 *)sWo)[i] = ((const float4 *)Wroot)[i];
    }
    if (tid < DD / 4) ((float4 *)sB)[tid] = ((const float4 *)brel)[tid];
    __syncthreads();

    int r0 = blockIdx.x * 256 + tid;
    int r1 = r0 + 128;
    bool v0 = r0 < nRows;
    bool v1 = r1 < nRows;
    if (!v0) return;  // r1 > r0, so nothing to do

    u64 acc0[32], acc1[32];
    const u64 *b2 = (const u64 *)sB;
#pragma unroll
    for (int c = 0; c < 32; c++) { acc0[c] = b2[c]; acc1[c] = b2[c]; }

    const float4 zero4 = make_float4(0.f, 0.f, 0.f, 0.f);

#pragma unroll 1
    for (int kk = 0; kk < 16; kk++) {
        float4 av0 = A4[(size_t)r0 * 16 + kk];
        float4 hv0 = H4[(size_t)r0 * 16 + kk];
        float4 av1 = v1 ? A4[(size_t)r1 * 16 + kk] : zero4;
        float4 hv1 = v1 ? H4[(size_t)r1 * 16 + kk] : zero4;
#pragma unroll
        for (int j = 0; j < 4; j++) {
            int k = kk * 4 + j;
            u64 a20 = pack2((&av0.x)[j]);
            u64 h20 = pack2((&hv0.x)[j]);
            u64 a21 = pack2((&av1.x)[j]);
            u64 h21 = pack2((&hv1.x)[j]);
            const ulonglong2 *wr = (const ulonglong2 *)(sWr + k * DD);
            const ulonglong2 *wo = (const ulonglong2 *)(sWo + k * DD);
#pragma unroll
            for (int c = 0; c < 16; c++) {
                ulonglong2 w1v = wr[c];
                fma2(acc0[2 * c],     a20, w1v.x);
                fma2(acc0[2 * c + 1], a20, w1v.y);
                fma2(acc1[2 * c],     a21, w1v.x);
                fma2(acc1[2 * c + 1], a21, w1v.y);
                ulonglong2 w2v = wo[c];
                fma2(acc0[2 * c],     h20, w2v.x);
                fma2(acc0[2 * c + 1], h20, w2v.y);
                fma2(acc1[2 * c],     h21, w2v.x);
                fma2(acc1[2 * c + 1], h21, w2v.y);
            }
        }
    }

    // epilogue
    if (!isLast) {
#pragma unroll
        for (int c = 0; c < 16; c++) {
            float4 o;
            float lo, hi;
            unpack2(acc0[2 * c], lo, hi);
            o.x = fmaxf(lo, 0.f); o.y = fmaxf(hi, 0.f);
            unpack2(acc0[2 * c + 1], lo, hi);
            o.z = fmaxf(lo, 0.f); o.w = fmaxf(hi, 0.f);
            Out4[(size_t)r0 * 16 + c] = o;
        }
        if (v1) {
#pragma unroll
            for (int c = 0; c < 16; c++) {
                float4 o;
                float lo, hi;
                unpack2(acc1[2 * c], lo, hi);
                o.x = fmaxf(lo, 0.f); o.y = fmaxf(hi, 0.f);
                unpack2(acc1[2 * c + 1], lo, hi);
                o.z = fmaxf(lo, 0.f); o.w = fmaxf(hi, 0.f);
                Out4[(size_t)r1 * 16 + c] = o;
            }
        }
    } else {
        // fused global_add_pool: relu'ed row -> pool[batch[row]]
        int g0 = batch[r0];
        float *p0 = pool + (size_t)g0 * DD;
#pragma unroll
        for (int c = 0; c < 16; c++) {
            float lo, hi, z, w;
            unpack2(acc0[2 * c], lo, hi);
            unpack2(acc0[2 * c + 1], z, w);
            lo = fmaxf(lo, 0.f); hi = fmaxf(hi, 0.f);
            z = fmaxf(z, 0.f);  w = fmaxf(w, 0.f);
            asm volatile("red.global.add.v4.f32 [%0], {%1, %2, %3, %4};"
                         :: "l"(p0 + c * 4), "f"(lo), "f"(hi), "f"(z), "f"(w)
                         : "memory");
        }
        if (v1) {
            int g1 = batch[r1];
            float *p1 = pool + (size_t)g1 * DD;
#pragma unroll
            for (int c = 0; c < 16; c++) {
                float lo, hi, z, w;
                unpack2(acc1[2 * c], lo, hi);
                unpack2(acc1[2 * c + 1], z, w);
                lo = fmaxf(lo, 0.f); hi = fmaxf(hi, 0.f);
                z = fmaxf(z, 0.f);  w = fmaxf(w, 0.f);
                asm volatile("red.global.add.v4.f32 [%0], {%1, %2, %3, %4};"
                             :: "l"(p1 + c * 4), "f"(lo), "f"(hi), "f"(z), "f"(w)
                             : "memory");
            }
        }
    }
}

// y = relu(pool @ W1 + b1) @ W2 + b2 ; one warp per graph, 4 graphs per block.
__global__ void head_kernel(const float *__restrict__ pool,
                            const float *__restrict__ W1,
                            const float *__restrict__ b1,
                            const float *__restrict__ W2,
                            const float *__restrict__ b2,
                            float *__restrict__ out) {
    __shared__ float st[4][DD];
    int w = threadIdx.x >> 5;
    int lane = threadIdx.x & 31;
    int g = blockIdx.x * 4 + w;

    float acc0 = b1[lane];
    float acc1 = b1[lane + 32];
#pragma unroll 4
    for (int k = 0; k < DD; k++) {
        float pv = pool[g * DD + k];
        acc0 += pv * W1[k * DD + lane];
        acc1 += pv * W1[k * DD + lane + 32];
    }
    st[w][lane] = fmaxf(acc0, 0.f);
    st[w][lane + 32] = fmaxf(acc1, 0.f);
    __syncwarp();

    if (lane < OUTD) {
        float acc = b2[lane];
#pragma unroll 4
        for (int k = 0; k < DD; k++) acc += st[w][k] * W2[k * OUTD + lane];
        out[g * OUTD + lane] = acc;
    }
}

extern "C" void kernel_launch(void *const *d_in, const int *in_sizes, int n_in,
                              void *d_out, int out_size) {
    const float *x     = (const float *)d_in[0];
    const int   *ei    = (const int *)d_in[1];
    const int   *batch = (const int *)d_in[2];
    const float *Wrel  = (const float *)d_in[3];
    const float *brel  = (const float *)d_in[4];
    const float *Wroot = (const float *)d_in[5];
    const float *W1    = (const float *)d_in[6];
    const float *b1    = (const float *)d_in[7];
    const float *W2    = (const float *)d_in[8];
    const float *b2    = (const float *)d_in[9];

    int nE = in_sizes[1] / 2;
    int nN = in_sizes[0] / DD;
    const int *src = ei;
    const int *dst = ei + nE;

    float *bufA, *bufB, *agg, *pool;
    int *rowStart, *cursor, *bsum, *csrSrc;
    cudaGetSymbolAddress((void **)&bufA, g_bufA);
    cudaGetSymbolAddress((void **)&bufB, g_bufB);
    cudaGetSymbolAddress((void **)&agg, g_agg);
    cudaGetSymbolAddress((void **)&pool, g_pool);
    cudaGetSymbolAddress((void **)&rowStart, g_rowStart);
    cudaGetSymbolAddress((void **)&cursor, g_cursor);
    cudaGetSymbolAddress((void **)&bsum, g_bsum);
    cudaGetSymbolAddress((void **)&csrSrc, g_csrSrc);

    // ---- one-kernel CSR build + pool zero ----
    int poolN4 = NG * 16;
    csr_mega_kernel<<<MEGA_CTAS, MEGA_THREADS>>>(
        src, dst, nE, nN, rowStart, cursor, csrSrc, bsum,
        (float4 *)pool, poolN4);

    const float *hcur = x;
    float *houts[NL] = {bufA, bufB, bufA, bufB};

    int gatherThreads = nN * 16;
    int nTiles = (nN + 255) / 256;
    for (int l = 0; l < NL; l++) {
        int isLast = (l == NL - 1);
        gather_kernel<<<(gatherThreads + 255) / 256, 256>>>(
            (const ulonglong2 *)hcur, rowStart, csrSrc,
            (ulonglong2 *)agg, nN);
        layer_kernel<<<nTiles, 128>>>(
            (const float4 *)agg, (const float4 *)hcur,
            Wrel + (size_t)l * DD * DD, Wroot + (size_t)l * DD * DD,
            brel + (size_t)l * DD, (float4 *)houts[l],
            batch, pool, nN, isLast);
        hcur = houts[l];
    }

    head_kernel<<<NG / 4, 128>>>(pool, W1, b1, W2, b2, (float *)d_out);
}